// round 15
// baseline (speedup 1.0000x reference)
#include <cuda_runtime.h>
#include <cuda_fp16.h>
#include <math.h>

#define BB 64
#define NTOK 2304
#define DD 64
#define NHEADS 8
#define TOKENS (BB*NTOK)   // 147456

#define WSCALE 4096.0f
#define WINV   (1.0f/4096.0f)

// ---------------- scratch (device globals; no allocations) ----------------
__device__ float g_xn[TOKENS*DD];                // [token][d]
__device__ float g_v[TOKENS*DD];                 // head-major: [(b*8+h)*2304 + p]*8 + j
__device__ float g_logits[BB*NHEADS*NTOK];
__device__ unsigned g_clsh[(size_t)TOKENS*4*32]; // fp16x2: [tok][r][32 pairs (2k,2k+1)]
__device__ float g_WL[NHEADS*DD];
__device__ float g_bL[NHEADS];
__device__ float g_vc[DD];
__device__ float g_clslogit[NHEADS];
__device__ float g_cvec[DD];
__device__ float g_cvecp[NHEADS*DD];             // per-head bwproj fold
__device__ uint2 g_P4h[NHEADS*1024];   // fp16x4 scaled: [h][f2][lane]
__device__ uint2 g_Q4h[NHEADS*1024];   // fp16x4 scaled: [h][e2][lane]
__device__ float g_u2[NHEADS*DD];

__device__ __forceinline__ float kscale() { return 0.35355339059327373f; } // 8^-0.5

// ---------------- f32x2 / fp16 helpers ----------------
typedef unsigned long long ull;
__device__ __forceinline__ ull pack2(float x, float y) {
    ull r; asm("mov.b64 %0, {%1,%2};" : "=l"(r) : "f"(x), "f"(y)); return r;
}
__device__ __forceinline__ void unpack2(ull v, float& x, float& y) {
    asm("mov.b64 {%0,%1}, %2;" : "=f"(x), "=f"(y) : "l"(v));
}
__device__ __forceinline__ void ffma2(ull& acc, ull a, ull b) {
    asm("fma.rn.f32x2 %0, %1, %2, %0;" : "+l"(acc) : "l"(a), "l"(b));
}
__device__ __forceinline__ unsigned h2pack(float a, float b) {
    __half2 h = __floats2half2_rn(a, b);
    return *reinterpret_cast<unsigned*>(&h);
}
__device__ __forceinline__ float2 h2f2(unsigned h) {
    __half2 hh = *reinterpret_cast<__half2*>(&h);
    return __half22float2(hh);
}
__device__ __forceinline__ ull h2ull(unsigned h) {
    float2 f = h2f2(h);
    return pack2(f.x, f.y);
}

#define SBUF 4160   // padded 64x64 buffer

// ---------------- single precompute kernel: 17 blocks ----------------
__global__ void __launch_bounds__(256) precomp(
    const float* __restrict__ cls_tok,
    const float* __restrict__ Wwqkv, const float* __restrict__ bwqkv,
    const float* __restrict__ brao,
    const float* __restrict__ Wout, const float* __restrict__ bout,
    const float* __restrict__ Wraq, const float* __restrict__ Wrak,
    const float* __restrict__ Wrao, const float* __restrict__ Wrav,
    const float* __restrict__ Wqkv, const float* __restrict__ bqkv,
    const float* __restrict__ Wwproj, const float* __restrict__ bwproj)
{
    extern __shared__ float s[];
    float* s0 = s;
    float* s1 = s + SBUF;
    float* s2 = s + 2*SBUF;
    int bid = blockIdx.x, tid = threadIdx.x;

    if (bid == 0) {
        __shared__ float scq[192];
        __shared__ float sqc[64];
        __shared__ float sred[256];
        if (tid < 192) {
            float a = bwqkv[tid];
            for (int d = 0; d < 64; d++) a += Wwqkv[tid*64+d]*cls_tok[d];
            scq[tid] = a;
        }
        __syncthreads();
        if (tid < 64) { sqc[tid] = scq[tid]*kscale(); g_vc[tid] = scq[128+tid]; }
        __syncthreads();
        if (tid < 8) {
            float cl = 0.f, bl = 0.f;
            for (int j = 0; j < 8; j++) {
                cl += sqc[tid*8+j]*scq[64+tid*8+j];
                bl += sqc[tid*8+j]*bwqkv[64+tid*8+j];
            }
            g_clslogit[tid] = cl; g_bL[tid] = bl;
        }
        for (int i = tid; i < 512; i += 256) {
            int h = i>>6, d = i&63;
            float a = 0.f;
            for (int j = 0; j < 8; j++) a += sqc[h*8+j]*Wwqkv[(64+h*8+j)*64+d];
            g_WL[i] = a;
        }
        {
            int o = tid>>2, q = tid&3;
            float a = (q==0) ? bout[o] : 0.f;
            for (int k = q*128; k < q*128+128; k++) a += Wout[o*512+k]*brao[k&63];
            sred[tid] = a;
        }
        __syncthreads();
        if (tid < 64)
            g_cvec[tid] = sred[4*tid] + sred[4*tid+1] + sred[4*tid+2] + sred[4*tid+3];
    }
    else if (bid <= 8) {
        // ---- P side ----
        int h = bid - 1;
        __shared__ float su[64];
        for (int i = tid; i < 4096; i += 256) { s0[i] = Wraq[i]; s1[i] = Wrak[i]; }
        __syncthreads();
        for (int i = tid; i < 4096; i += 256) {           // G[dd][g] -> s2
            int dd = i>>6, g = i&63;
            float a = 0.f;
            #pragma unroll 8
            for (int e = 0; e < 64; e++) a += s0[e*64+dd]*s1[e*64+g];
            s2[i] = a;
        }
        __syncthreads();
        for (int i = tid; i < 4096; i += 256) s0[i] = Wqkv[h*4096 + i];
        __syncthreads();
        for (int i = tid; i < 4096; i += 256) {           // P[f][g] -> s1
            int f = i>>6, g = i&63;
            float a = 0.f;
            #pragma unroll 8
            for (int dd = 0; dd < 64; dd++) a += s0[dd*64+f]*s2[dd*64+g];
            s1[i] = a*kscale();
        }
        if (tid < 64) {
            float a = 0.f;
            for (int dd = 0; dd < 64; dd++) a += bqkv[h*64+dd]*s2[dd*64+tid];
            su[tid] = a*kscale();
        }
        __syncthreads();
        for (int i = tid; i < 4096; i += 256) s0[i] = Wwproj[i];
        __syncthreads();
        for (int i = tid; i < 4096; i += 256) {           // P2[f][e] -> s2
            int f = i>>6, e = i&63;
            float a = 0.f;
            #pragma unroll 8
            for (int g = 0; g < 64; g++) a += s1[f*64+g]*s0[g*64+e];
            s2[i] = a;
        }
        if (tid < 64) {
            float a = 0.f;
            for (int g = 0; g < 64; g++) a += su[g]*s0[g*64+tid];
            g_u2[h*64+tid] = a;
        }
        __syncthreads();
        for (int i = tid; i < 1024; i += 256) {
            int k2 = i>>5, l = i&31;
            uint2 u;
            u.x = h2pack(s2[(2*k2)*64+l]*WSCALE,   s2[(2*k2)*64+l+32]*WSCALE);
            u.y = h2pack(s2[(2*k2+1)*64+l]*WSCALE, s2[(2*k2+1)*64+l+32]*WSCALE);
            g_P4h[h*1024+i] = u;
        }
    }
    else {
        // ---- Q side ----
        int h = bid - 9;
        for (int i = tid; i < 4096; i += 256) { s0[i] = Wrao[i]; s1[i] = Wrav[i]; }
        __syncthreads();
        for (int i = tid; i < 4096; i += 256) {           // R[a][g] -> s2
            int a_ = i>>6, g = i&63;
            float a = 0.f;
            #pragma unroll 8
            for (int c = 0; c < 64; c++) a += s0[a_*64+c]*s1[c*64+g];
            s2[i] = a;
        }
        __syncthreads();
        for (int i = tid; i < 4096; i += 256) {
            int o = i>>6, a_ = i&63;
            s0[i] = Wout[o*512 + h*64 + a_];
        }
        __syncthreads();
        for (int i = tid; i < 4096; i += 256) {           // Qt[o][g] -> s1
            int o = i>>6, g = i&63;
            float a = 0.f;
            #pragma unroll 8
            for (int a_ = 0; a_ < 64; a_++) a += s0[o*64+a_]*s2[a_*64+g];
            s1[i] = a;
        }
        __syncthreads();
        if (tid < 64) {
            float a = 0.f;
            for (int g = 0; g < 64; g++) a += bwproj[g]*s1[tid*64+g];
            g_cvecp[h*64+tid] = a;
        }
        for (int i = tid; i < 4096; i += 256) s0[i] = Wwproj[i];
        __syncthreads();
        for (int i = tid; i < 4096; i += 256) {           // Q2t[o][e] -> s2 (65-stride)
            int o = i>>6, e = i&63;
            float a = 0.f;
            #pragma unroll 8
            for (int g = 0; g < 64; g++) a += s0[g*64+e]*s1[o*64+g];
            s2[o*65+e] = a;
        }
        __syncthreads();
        for (int i = tid; i < 1024; i += 256) {
            int k2 = i>>5, l = i&31;
            uint2 u;
            u.x = h2pack(s2[l*65 + 2*k2]*WSCALE,     s2[(l+32)*65 + 2*k2]*WSCALE);
            u.y = h2pack(s2[l*65 + 2*k2 + 1]*WSCALE, s2[(l+32)*65 + 2*k2 + 1]*WSCALE);
            g_Q4h[h*1024+i] = u;
        }
    }
}

// ---------------- K1: LayerNorm + logits + v projection ----------------
__global__ void __launch_bounds__(256) k_ln(const float* __restrict__ x,
     const float* __restrict__ ln_g, const float* __restrict__ ln_b,
     const float* __restrict__ Wwqkv, const float* __restrict__ bwqkv)
{
    __shared__ float sfw[4096];
    __shared__ float sWL[8*65];
    __shared__ float sxb[8*64];
    int tid = threadIdx.x, warp = tid>>5, lane = tid&31;
    for (int idx = tid; idx < 4096; idx += 256) {
        int c = idx&3, l = (idx>>2)&31, d2 = idx>>7;
        int e = l + 32*(c&1);
        int d = 2*d2 + (c>>1);
        sfw[idx] = Wwqkv[8192 + e*64 + d];
    }
    for (int i = tid; i < 512; i += 256)
        sWL[(i>>6)*65 + (i&63)] = g_WL[i];
    __syncthreads();
    float ga0 = ln_g[lane], ga1 = ln_g[lane+32];
    float gb0 = ln_b[lane], gb1 = ln_b[lane+32];
    float bv0 = bwqkv[128+lane], bv1 = bwqkv[128+lane+32];
    int tok_base = blockIdx.x*64 + warp*8;
    int b = tok_base/NTOK;
    int hh = lane>>2, qq = lane&3;
    for (int t = 0; t < 8; t++) {
        int token = tok_base + t;
        float x0 = x[token*64 + lane];
        float x1 = x[token*64 + lane + 32];
        float s = x0 + x1, ss = x0*x0 + x1*x1;
        #pragma unroll
        for (int off = 16; off; off >>= 1) {
            s  += __shfl_xor_sync(0xffffffffu, s,  off);
            ss += __shfl_xor_sync(0xffffffffu, ss, off);
        }
        float mu = s*(1.f/64.f);
        float var = ss*(1.f/64.f) - mu*mu;
        float rstd = rsqrtf(var + 1e-5f);
        float xn0 = (x0-mu)*rstd*ga0 + gb0;
        float xn1 = (x1-mu)*rstd*ga1 + gb1;
        g_xn[(size_t)token*64+lane] = xn0;
        g_xn[(size_t)token*64+lane+32] = xn1;
        sxb[warp*64+lane] = xn0; sxb[warp*64+lane+32] = xn1;
        __syncwarp();
        ull acc = pack2(bv0, bv1);
        #pragma unroll 8
        for (int d2 = 0; d2 < 32; d2++) {
            float4 w = *(const float4*)(sfw + d2*128 + lane*4);
            float2 xp = *(const float2*)(sxb + warp*64 + 2*d2);
            ffma2(acc, pack2(xp.x, xp.x), pack2(w.x, w.y));
            ffma2(acc, pack2(xp.y, xp.y), pack2(w.z, w.w));
        }
        float v0, v1; unpack2(acc, v0, v1);
        int nn = token - b*NTOK;
        {
            int h0 = lane>>3, j0 = lane&7;
            g_v[((size_t)(b*8+h0)*NTOK + nn)*8 + j0] = v0;
            int h1 = (lane+32)>>3;
            g_v[((size_t)(b*8+h1)*NTOK + nn)*8 + j0] = v1;
        }
        {
            float a = 0.f;
            #pragma unroll
            for (int dd = 0; dd < 16; dd++)
                a += sxb[warp*64 + qq*16 + dd]*sWL[hh*65 + qq*16 + dd];
            a += __shfl_xor_sync(0xffffffffu, a, 1);
            a += __shfl_xor_sync(0xffffffffu, a, 2);
            if (qq == 0) g_logits[(b*8+hh)*NTOK + nn] = a + g_bL[hh];
        }
        __syncwarp();
    }
}

// ---------------- K2: quad sums — parallel sub-row scans, fp16 cls out ----------------
#define CSTR 2369
__global__ void __launch_bounds__(512) k_quad()
{
    extern __shared__ float s[];  // 9 * CSTR floats
    __shared__ float red[512];
    __shared__ float smv;
    int bid = blockIdx.x, tid = threadIdx.x;
    int b = bid>>3, h = bid&7;
    for (int p = tid; p < 2304; p += 512) {
        int y = p/48, xx = p - y*48;
        s[y*49+xx] = g_logits[bid*NTOK + p];
    }
    __syncthreads();
    float mloc = -1e30f;
    for (int p = tid; p < 2304; p += 512) {
        int y = p/48, xx = p - y*48;
        mloc = fmaxf(mloc, s[y*49+xx]);
    }
    red[tid] = mloc;
    __syncthreads();
    for (int st = 256; st; st >>= 1) {
        if (tid < st) red[tid] = fmaxf(red[tid], red[tid+st]);
        __syncthreads();
    }
    if (tid == 0) smv = fmaxf(red[0], g_clslogit[h]);
    __syncthreads();
    float m = smv;
    float ecls = __expf(g_clslogit[h] - m);
    for (int p = tid; p < 2304; p += 512) {
        int y = p/48, xx = p - y*48;
        int idx = y*49+xx;
        s[idx] = __expf(s[idx] - m);
    }
    __syncthreads();
    const float* vbase = g_v + (size_t)bid*NTOK*8;
    for (int p = tid; p < 2304; p += 512) {
        int y = p/48, xx = p - y*48;
        int base = y*49 + xx;
        float ev = s[base];
        float4 va = *(const float4*)(vbase + (size_t)p*8);
        float4 vb = *(const float4*)(vbase + (size_t)p*8 + 4);
        s[1*CSTR + base] = ev*va.x;
        s[2*CSTR + base] = ev*va.y;
        s[3*CSTR + base] = ev*va.z;
        s[4*CSTR + base] = ev*va.w;
        s[5*CSTR + base] = ev*vb.x;
        s[6*CSTR + base] = ev*vb.y;
        s[7*CSTR + base] = ev*vb.z;
        s[8*CSTR + base] = ev*vb.w;
    }
    __syncthreads();
    {
        int sub = tid & 7;
        for (int rid = tid>>3; rid < 432; rid += 64) {
            int ch = rid/48, y = rid - (rid/48)*48;
            float* row = s + ch*CSTR + y*49 + sub*6;
            float p0 = row[0], p1 = row[1], p2 = row[2];
            float p3 = row[3], p4 = row[4], p5 = row[5];
            p1 += p0; p2 += p1; p3 += p2; p4 += p3; p5 += p4;
            float inc = p5;
            #pragma unroll
            for (int d = 1; d < 8; d <<= 1) {
                float vsh = __shfl_up_sync(0xffffffffu, inc, d, 8);
                if (sub >= d) inc += vsh;
            }
            float off = inc - p5;
            row[0] = p0+off; row[1] = p1+off; row[2] = p2+off;
            row[3] = p3+off; row[4] = p4+off; row[5] = p5+off;
        }
    }
    __syncthreads();
    {
        int sub = tid & 7;
        for (int cid = tid>>3; cid < 432; cid += 64) {
            int ch = cid/48, xx = cid - (cid/48)*48;
            float* col = s + ch*CSTR + xx + sub*6*49;
            float p0 = col[0],     p1 = col[49],    p2 = col[98];
            float p3 = col[147],   p4 = col[196],   p5 = col[245];
            p1 += p0; p2 += p1; p3 += p2; p4 += p3; p5 += p4;
            float inc = p5;
            #pragma unroll
            for (int d = 1; d < 8; d <<= 1) {
                float vsh = __shfl_up_sync(0xffffffffu, inc, d, 8);
                if (sub >= d) inc += vsh;
            }
            float off = inc - p5;
            col[0]   = p0+off; col[49]  = p1+off; col[98]  = p2+off;
            col[147] = p3+off; col[196] = p4+off; col[245] = p5+off;
        }
    }
    __syncthreads();
    float vc[8];
    #pragma unroll
    for (int j = 0; j < 8; j++) vc[j] = g_vc[h*8+j];
    for (int p = tid; p < 2304; p += 512) {
        int y = p/48, xx = p - y*48;
        int iC  = y*49 + xx;
        int iRT = y*49 + 47;
        int iCB = 47*49 + xx;
        int iT  = 47*49 + 47;
        int iCm = iC - 1;
        int iUp = iC - 49;
        int iUR = iRT - 49;
        int iCL = iCB - 1;
        int iUL = iUp - 1;
        bool hx = xx > 0, hy = y > 0;
        float rd[4];
        {
            const float* C = s;
            float tl = C[iC];
            float tr = C[iRT] - (hx ? C[iCm] : 0.f);
            float bl = C[iCB] - (hy ? C[iUp] : 0.f);
            float br = C[iT] - (hy ? C[iUR] : 0.f) - (hx ? C[iCL] : 0.f) + ((hx&&hy) ? C[iUL] : 0.f);
            rd[0] = 1.f/(ecls+tl); rd[1] = 1.f/(ecls+tr);
            rd[2] = 1.f/(ecls+bl); rd[3] = 1.f/(ecls+br);
        }
        float out[4][8];
        #pragma unroll
        for (int j = 0; j < 8; j++) {
            const float* C = s + (1+j)*CSTR;
            float tl = C[iC];
            float tr = C[iRT] - (hx ? C[iCm] : 0.f);
            float bl = C[iCB] - (hy ? C[iUp] : 0.f);
            float br = C[iT] - (hy ? C[iUR] : 0.f) - (hx ? C[iCL] : 0.f) + ((hx&&hy) ? C[iUL] : 0.f);
            float base = ecls*vc[j];
            out[0][j] = (base+tl)*rd[0];
            out[1][j] = (base+tr)*rd[1];
            out[2][j] = (base+bl)*rd[2];
            out[3][j] = (base+br)*rd[3];
        }
        unsigned* op = g_clsh + ((size_t)(b*NTOK + p)*4)*32 + h*4;
        #pragma unroll
        for (int r = 0; r < 4; r++) {
            uint4 u;
            u.x = h2pack(out[r][0], out[r][1]);
            u.y = h2pack(out[r][2], out[r][3]);
            u.z = h2pack(out[r][4], out[r][5]);
            u.w = h2pack(out[r][6], out[r][7]);
            *(uint4*)(op + r*32) = u;
        }
    }
}

// ---------------- K3: fused epilogue — fp16 weights + fp16 cls + fp16 cmix ----------------
#define XS 68
#define MSTR 34   // scmix_h2 row stride in uints (uint2 accesses only: 8B-aligned)
__global__ void __launch_bounds__(256) k_epi(float* __restrict__ outp)
{
    extern __shared__ float s[];
    float*    sxn = s;                          // [64 f][XS] fp32
    unsigned* smh = (unsigned*)(s + 64*XS);     // [64 e][MSTR] fp16x2 token-pairs
    uint2*    wsP = (uint2*)(s + 64*XS + 64*MSTR);
    uint2*    wsQ = wsP + 1024;
    __shared__ float scv[64];
    int tid = threadIdx.x, warp = tid>>5, lane = tid&31;
    int tok0 = blockIdx.x*64;
    int tb = warp*8;

    if (tid < 64) {
        float a = g_cvec[tid];
        #pragma unroll
        for (int h = 0; h < 8; h++) a += g_cvecp[h*64+tid];
        scv[tid] = a;
    }
    for (int i = tid; i < 4096; i += 256) {
        int t = i>>6, d = i&63;
        sxn[d*XS + t] = g_xn[(size_t)(tok0+t)*64 + d];
    }

    ull accO[2][4];
    #pragma unroll
    for (int e = 0; e < 2; e++)
        #pragma unroll
        for (int pr = 0; pr < 4; pr++) accO[e][pr] = pack2(0.f, 0.f);

    for (int h = 0; h < 8; h++) {
        __syncthreads();
        for (int i = tid; i < 1024; i += 256) {
            wsP[i] = g_P4h[h*1024 + i];
            wsQ[i] = g_Q4h[h*1024 + i];
        }
        __syncthreads();

        // GEMV1 (scaled domain)
        ull aQ[2][4];
        #pragma unroll
        for (int pr = 0; pr < 4; pr++) { aQ[0][pr] = pack2(0.f,0.f); aQ[1][pr] = pack2(0.f,0.f); }
        #pragma unroll 8
        for (int f2 = 0; f2 < 32; f2++) {
            uint2 wp = wsP[f2*32 + lane];
            float2 wa = h2f2(wp.x);
            float2 wb = h2f2(wp.y);
            ull pa0 = pack2(wa.x, wa.x);
            ull pa1 = pack2(wa.y, wa.y);
            ull pb0 = pack2(wb.x, wb.x);
            ull pb1 = pack2(wb.y, wb.y);
            const ulonglong2* xr0 = (const ulonglong2*)(sxn + (2*f2)*XS + tb);
            const ulonglong2* xr1 = (const ulonglong2*)(sxn + (2*f2+1)*XS + tb);
            ulonglong2 xa = xr0[0], xb = xr0[1];
            ulonglong2 xc = xr1[0], xd = xr1[1];
            ffma2(aQ[0][0], xa.x, pa0); ffma2(aQ[0][1], xa.y, pa0);
            ffma2(aQ[0][2], xb.x, pa0); ffma2(aQ[0][3], xb.y, pa0);
            ffma2(aQ[1][0], xa.x, pa1); ffma2(aQ[1][1], xa.y, pa1);
            ffma2(aQ[1][2], xb.x, pa1); ffma2(aQ[1][3], xb.y, pa1);
            ffma2(aQ[0][0], xc.x, pb0); ffma2(aQ[0][1], xc.y, pb0);
            ffma2(aQ[0][2], xd.x, pb0); ffma2(aQ[0][3], xd.y, pb0);
            ffma2(aQ[1][0], xc.x, pb1); ffma2(aQ[1][1], xc.y, pb1);
            ffma2(aQ[1][2], xd.x, pb1); ffma2(aQ[1][3], xd.y, pb1);
        }
        float u2a = g_u2[h*64 + lane];
        float u2b = g_u2[h*64 + lane + 32];
        float q0[8], q1[8];
        #pragma unroll
        for (int pr = 0; pr < 4; pr++) {
            float a0, a1, b0, b1;
            unpack2(aQ[0][pr], a0, a1);
            unpack2(aQ[1][pr], b0, b1);
            q0[2*pr]   = a0*WINV + u2a; q0[2*pr+1] = a1*WINV + u2a;
            q1[2*pr]   = b0*WINV + u2b; q1[2*pr+1] = b1*WINV + u2b;
        }

        // scores + softmax + cmix (fp16 cls, pairs (2l,2l+1))
        unsigned ubA[4], ubB[4];
        float cmAp = 0.f, cmBp = 0.f;
        #pragma unroll
        for (int t = 0; t < 8; t++) {
            int i0 = (2*lane) & 31;
            int i1 = (2*lane+1) & 31;
            float s0a = __shfl_sync(0xffffffffu, q0[t], i0);
            float s1a = __shfl_sync(0xffffffffu, q1[t], i0);
            float s0b = __shfl_sync(0xffffffffu, q0[t], i1);
            float s1b = __shfl_sync(0xffffffffu, q1[t], i1);
            float qa = (lane < 16) ? s0a : s1a;
            float qb = (lane < 16) ? s0b : s1b;
            const unsigned* cp = g_clsh + ((size_t)(tok0 + tb + t)*4)*32 + lane;
            float2 c0 = h2f2(cp[0]);
            float2 c1 = h2f2(cp[32]);
            float2 c2 = h2f2(cp[64]);
            float2 c3 = h2f2(cp[96]);
            float sc0 = qa*c0.x + qb*c0.y;
            float sc1 = qa*c1.x + qb*c1.y;
            float sc2 = qa*c2.x + qb*c2.y;
            float sc3 = qa*c3.x + qb*c3.y;
            #pragma unroll
            for (int off = 16; off; off >>= 1) {
                sc0 += __shfl_xor_sync(0xffffffffu, sc0, off);
                sc1 += __shfl_xor_sync(0xffffffffu, sc1, off);
                sc2 += __shfl_xor_sync(0xffffffffu, sc2, off);
                sc3 += __shfl_xor_sync(0xffffffffu, sc3, off);
            }
            float mx = fmaxf(fmaxf(sc0,sc1), fmaxf(sc2,sc3));
            float e0 = __expf(sc0-mx), e1 = __expf(sc1-mx);
            float e2 = __expf(sc2-mx), e3 = __expf(sc3-mx);
            float inv = 1.f/(e0+e1+e2+e3);
            float a0 = e0*inv, a1 = e1*inv, a2 = e2*inv, a3 = e3*inv;
            float cmA = a0*c0.x + a1*c1.x + a2*c2.x + a3*c3.x;
            float cmB = a0*c0.y + a1*c1.y + a2*c2.y + a3*c3.y;
            if (t & 1) {
                ubA[t>>1] = h2pack(cmAp, cmA);
                ubB[t>>1] = h2pack(cmBp, cmB);
            } else { cmAp = cmA; cmBp = cmB; }
        }
        {
            unsigned* d0 = smh + (2*lane)*MSTR   + warp*4;
            unsigned* d1 = smh + (2*lane+1)*MSTR + warp*4;
            *(uint2*)(d0)     = make_uint2(ubA[0], ubA[1]);
            *(uint2*)(d0 + 2) = make_uint2(ubA[2], ubA[3]);
            *(uint2*)(d1)     = make_uint2(ubB[0], ubB[1]);
            *(uint2*)(d1 + 2) = make_uint2(ubB[2], ubB[3]);
        }
        __syncwarp();

        // GEMV2 (scaled domain), fp16 cmix token-pairs
        #pragma unroll 8
        for (int e2 = 0; e2 < 32; e2++) {
            uint2 wq = wsQ[e2*32 + lane];
            float2 wa = h2f2(wq.x);
            float2 wb = h2f2(wq.y);
            ull pa0 = pack2(wa.x, wa.x);
            ull pa1 = pack2(wa.y, wa.y);
            ull pb0 = pack2(wb.x, wb.x);
            ull pb1 = pack2(wb.y, wb.y);
            const unsigned* r0 = smh + (2*e2)*MSTR   + warp*4;
            const unsigned* r1 = smh + (2*e2+1)*MSTR + warp*4;
            uint2 m0a = *(const uint2*)(r0);
            uint2 m0b = *(const uint2*)(r0 + 2);
            uint2 m1a = *(const uint2*)(r1);
            uint2 m1b = *(const uint2*)(r1 + 2);
            ull ma0 = h2ull(m0a.x), ma1 = h2ull(m0a.y), ma2 = h2ull(m0b.x), ma3 = h2ull(m0b.y);
            ull mb0 = h2ull(m1a.x), mb1 = h2ull(m1a.y), mb2 = h2ull(m1b.x), mb3 = h2ull(m1b.y);
            ffma2(accO[0][0], ma0, pa0); ffma2(accO[0][1], ma1, pa0);
            ffma2(accO[0][2], ma2, pa0); ffma2(accO[0][3], ma3, pa0);
            ffma2(accO[1][0], ma0, pa1); ffma2(accO[1][1], ma1, pa1);
            ffma2(accO[1][2], ma2, pa1); ffma2(accO[1][3], ma3, pa1);
            ffma2(accO[0][0], mb0, pb0); ffma2(accO[0][1], mb1, pb0);
            ffma2(accO[0][2], mb2, pb0); ffma2(accO[0][3], mb3, pb0);
            ffma2(accO[1][0], mb0, pb1); ffma2(accO[1][1], mb1, pb1);
            ffma2(accO[1][2], mb2, pb1); ffma2(accO[1][3], mb3, pb1);
        }
    }

    float o0[8], o1[8];
    #pragma unroll
    for (int pr = 0; pr < 4; pr++) {
        unpack2(accO[0][pr], o0[2*pr], o0[2*pr+1]);
        unpack2(accO[1][pr], o1[2*pr], o1[2*pr+1]);
    }
    float c0 = scv[lane], c1 = scv[lane+32];
    #pragma unroll
    for (int t = 0; t < 8; t++) {
        outp[(size_t)(tok0+tb+t)*64 + lane]      = o0[t]*WINV + c0;
        outp[(size_t)(tok0+tb+t)*64 + lane + 32] = o1[t]*WINV + c1;
    }
}

// ---------------- launch ----------------
extern "C" void kernel_launch(void* const* d_in, const int* in_sizes, int n_in,
                              void* d_out, int out_size)
{
    const float* x      = (const float*)d_in[0];
    const float* ln_g   = (const float*)d_in[1];
    const float* ln_b   = (const float*)d_in[2];
    const float* Wqkv   = (const float*)d_in[3];
    const float* bqkv   = (const float*)d_in[4];
    const float* cls_t  = (const float*)d_in[5];
    const float* Wwqkv  = (const float*)d_in[6];
    const float* bwqkv  = (const float*)d_in[7];
    const float* Wwproj = (const float*)d_in[8];
    const float* bwproj = (const float*)d_in[9];
    const float* Wraq   = (const float*)d_in[10];
    const float* Wrak   = (const float*)d_in[11];
    const float* Wrav   = (const float*)d_in[12];
    const float* Wrao   = (const float*)d_in[13];
    const float* brao   = (const float*)d_in[14];
    const float* Wout   = (const float*)d_in[15];
    const float* bout   = (const float*)d_in[16];
    float* outp = (float*)d_out;

    int pre_smem  = 3*SBUF*4;                        // 49920 B
    int quad_smem = 9*CSTR*4;                        // 85284 B
    int epi_smem  = (64*XS + 64*MSTR)*4 + 2*1024*8;  // 26112 + 16384 = 42496 B
    cudaFuncSetAttribute(precomp, cudaFuncAttributeMaxDynamicSharedMemorySize, pre_smem);
    cudaFuncSetAttribute(k_quad,  cudaFuncAttributeMaxDynamicSharedMemorySize, quad_smem);
    cudaFuncSetAttribute(k_epi,   cudaFuncAttributeMaxDynamicSharedMemorySize, epi_smem);

    precomp<<<17, 256, pre_smem>>>(cls_t, Wwqkv, bwqkv, brao, Wout, bout,
                                   Wraq, Wrak, Wrao, Wrav, Wqkv, bqkv, Wwproj, bwproj);
    k_ln<<<TOKENS/64, 256>>>(x, ln_g, ln_b, Wwqkv, bwqkv);
    k_quad<<<BB*NHEADS, 512, quad_smem>>>();
    k_epi<<<TOKENS/64, 256, epi_smem>>>(outp);
}

// round 16
// speedup vs baseline: 1.1190x; 1.1190x over previous
#include <cuda_runtime.h>
#include <cuda_fp16.h>
#include <math.h>

#define BB 64
#define NTOK 2304
#define DD 64
#define NHEADS 8
#define TOKENS (BB*NTOK)   // 147456

#define WSCALE 4096.0f
#define WINV   (1.0f/4096.0f)

// ---------------- scratch (device globals; no allocations) ----------------
__device__ float g_xn[TOKENS*DD];                // [token][d]
__device__ float g_v[TOKENS*DD];                 // head-major: [(b*8+h)*2304 + p]*8 + j
__device__ float g_logits[BB*NHEADS*NTOK];
__device__ unsigned g_clsh[(size_t)TOKENS*4*32]; // fp16x2: [tok][r][32 pairs (2k,2k+1)]
__device__ float g_WL[NHEADS*DD];
__device__ float g_bL[NHEADS];
__device__ float g_vc[DD];
__device__ float g_clslogit[NHEADS];
__device__ float g_cvec[DD];
__device__ float g_cvecp[NHEADS*DD];             // per-head bwproj fold
__device__ uint2 g_P4h[NHEADS*1024];   // fp16x4 scaled: [h][f2][lane] = cols (2l,2l+1)
__device__ uint2 g_Q4h[NHEADS*1024];   // fp16x4 scaled: [h][e2][lane] = cols (l,l+32)
__device__ float g_u2[NHEADS*DD];

__device__ __forceinline__ float kscale() { return 0.35355339059327373f; } // 8^-0.5

// ---------------- f32x2 / fp16 helpers ----------------
typedef unsigned long long ull;
__device__ __forceinline__ ull pack2(float x, float y) {
    ull r; asm("mov.b64 %0, {%1,%2};" : "=l"(r) : "f"(x), "f"(y)); return r;
}
__device__ __forceinline__ void unpack2(ull v, float& x, float& y) {
    asm("mov.b64 {%0,%1}, %2;" : "=f"(x), "=f"(y) : "l"(v));
}
__device__ __forceinline__ void ffma2(ull& acc, ull a, ull b) {
    asm("fma.rn.f32x2 %0, %1, %2, %0;" : "+l"(acc) : "l"(a), "l"(b));
}
__device__ __forceinline__ unsigned h2pack(float a, float b) {
    __half2 h = __floats2half2_rn(a, b);
    return *reinterpret_cast<unsigned*>(&h);
}
__device__ __forceinline__ float2 h2f2(unsigned h) {
    __half2 hh = *reinterpret_cast<__half2*>(&h);
    return __half22float2(hh);
}

#define SBUF 4160   // padded 64x64 buffer

// ---------------- single precompute kernel: 17 blocks ----------------
__global__ void __launch_bounds__(256) precomp(
    const float* __restrict__ cls_tok,
    const float* __restrict__ Wwqkv, const float* __restrict__ bwqkv,
    const float* __restrict__ brao,
    const float* __restrict__ Wout, const float* __restrict__ bout,
    const float* __restrict__ Wraq, const float* __restrict__ Wrak,
    const float* __restrict__ Wrao, const float* __restrict__ Wrav,
    const float* __restrict__ Wqkv, const float* __restrict__ bqkv,
    const float* __restrict__ Wwproj, const float* __restrict__ bwproj)
{
    extern __shared__ float s[];
    float* s0 = s;
    float* s1 = s + SBUF;
    float* s2 = s + 2*SBUF;
    int bid = blockIdx.x, tid = threadIdx.x;

    if (bid == 0) {
        __shared__ float scq[192];
        __shared__ float sqc[64];
        __shared__ float sred[256];
        if (tid < 192) {
            float a = bwqkv[tid];
            for (int d = 0; d < 64; d++) a += Wwqkv[tid*64+d]*cls_tok[d];
            scq[tid] = a;
        }
        __syncthreads();
        if (tid < 64) { sqc[tid] = scq[tid]*kscale(); g_vc[tid] = scq[128+tid]; }
        __syncthreads();
        if (tid < 8) {
            float cl = 0.f, bl = 0.f;
            for (int j = 0; j < 8; j++) {
                cl += sqc[tid*8+j]*scq[64+tid*8+j];
                bl += sqc[tid*8+j]*bwqkv[64+tid*8+j];
            }
            g_clslogit[tid] = cl; g_bL[tid] = bl;
        }
        for (int i = tid; i < 512; i += 256) {
            int h = i>>6, d = i&63;
            float a = 0.f;
            for (int j = 0; j < 8; j++) a += sqc[h*8+j]*Wwqkv[(64+h*8+j)*64+d];
            g_WL[i] = a;
        }
        {
            int o = tid>>2, q = tid&3;
            float a = (q==0) ? bout[o] : 0.f;
            for (int k = q*128; k < q*128+128; k++) a += Wout[o*512+k]*brao[k&63];
            sred[tid] = a;
        }
        __syncthreads();
        if (tid < 64)
            g_cvec[tid] = sred[4*tid] + sred[4*tid+1] + sred[4*tid+2] + sred[4*tid+3];
    }
    else if (bid <= 8) {
        // ---- P side ----
        int h = bid - 1;
        __shared__ float su[64];
        for (int i = tid; i < 4096; i += 256) { s0[i] = Wraq[i]; s1[i] = Wrak[i]; }
        __syncthreads();
        for (int i = tid; i < 4096; i += 256) {           // G[dd][g] -> s2
            int dd = i>>6, g = i&63;
            float a = 0.f;
            #pragma unroll 8
            for (int e = 0; e < 64; e++) a += s0[e*64+dd]*s1[e*64+g];
            s2[i] = a;
        }
        __syncthreads();
        for (int i = tid; i < 4096; i += 256) s0[i] = Wqkv[h*4096 + i];
        __syncthreads();
        for (int i = tid; i < 4096; i += 256) {           // P[f][g] -> s1
            int f = i>>6, g = i&63;
            float a = 0.f;
            #pragma unroll 8
            for (int dd = 0; dd < 64; dd++) a += s0[dd*64+f]*s2[dd*64+g];
            s1[i] = a*kscale();
        }
        if (tid < 64) {
            float a = 0.f;
            for (int dd = 0; dd < 64; dd++) a += bqkv[h*64+dd]*s2[dd*64+tid];
            su[tid] = a*kscale();
        }
        __syncthreads();
        for (int i = tid; i < 4096; i += 256) s0[i] = Wwproj[i];
        __syncthreads();
        for (int i = tid; i < 4096; i += 256) {           // P2[f][e] -> s2
            int f = i>>6, e = i&63;
            float a = 0.f;
            #pragma unroll 8
            for (int g = 0; g < 64; g++) a += s1[f*64+g]*s0[g*64+e];
            s2[i] = a;
        }
        if (tid < 64) {
            float a = 0.f;
            for (int g = 0; g < 64; g++) a += su[g]*s0[g*64+tid];
            g_u2[h*64+tid] = a;
        }
        __syncthreads();
        // pack fp16 scaled, e-pairs (2l, 2l+1)
        for (int i = tid; i < 1024; i += 256) {
            int k2 = i>>5, l = i&31;
            uint2 u;
            u.x = h2pack(s2[(2*k2)*64 + 2*l]*WSCALE,   s2[(2*k2)*64 + 2*l+1]*WSCALE);
            u.y = h2pack(s2[(2*k2+1)*64 + 2*l]*WSCALE, s2[(2*k2+1)*64 + 2*l+1]*WSCALE);
            g_P4h[h*1024+i] = u;
        }
    }
    else {
        // ---- Q side ----
        int h = bid - 9;
        for (int i = tid; i < 4096; i += 256) { s0[i] = Wrao[i]; s1[i] = Wrav[i]; }
        __syncthreads();
        for (int i = tid; i < 4096; i += 256) {           // R[a][g] -> s2
            int a_ = i>>6, g = i&63;
            float a = 0.f;
            #pragma unroll 8
            for (int c = 0; c < 64; c++) a += s0[a_*64+c]*s1[c*64+g];
            s2[i] = a;
        }
        __syncthreads();
        for (int i = tid; i < 4096; i += 256) {
            int o = i>>6, a_ = i&63;
            s0[i] = Wout[o*512 + h*64 + a_];
        }
        __syncthreads();
        for (int i = tid; i < 4096; i += 256) {           // Qt[o][g] -> s1
            int o = i>>6, g = i&63;
            float a = 0.f;
            #pragma unroll 8
            for (int a_ = 0; a_ < 64; a_++) a += s0[o*64+a_]*s2[a_*64+g];
            s1[i] = a;
        }
        __syncthreads();
        if (tid < 64) {
            float a = 0.f;
            for (int g = 0; g < 64; g++) a += bwproj[g]*s1[tid*64+g];
            g_cvecp[h*64+tid] = a;
        }
        for (int i = tid; i < 4096; i += 256) s0[i] = Wwproj[i];
        __syncthreads();
        for (int i = tid; i < 4096; i += 256) {           // Q2t[o][e] -> s2 (65-stride)
            int o = i>>6, e = i&63;
            float a = 0.f;
            #pragma unroll 8
            for (int g = 0; g < 64; g++) a += s0[g*64+e]*s1[o*64+g];
            s2[o*65+e] = a;
        }
        __syncthreads();
        // pack fp16 scaled: Q2[e][o], o-pairs (l, l+32)
        for (int i = tid; i < 1024; i += 256) {
            int k2 = i>>5, l = i&31;
            uint2 u;
            u.x = h2pack(s2[l*65 + 2*k2]*WSCALE,     s2[(l+32)*65 + 2*k2]*WSCALE);
            u.y = h2pack(s2[l*65 + 2*k2 + 1]*WSCALE, s2[(l+32)*65 + 2*k2 + 1]*WSCALE);
            g_Q4h[h*1024+i] = u;
        }
    }
}

// ---------------- K1: LayerNorm + logits + v projection ----------------
__global__ void __launch_bounds__(256) k_ln(const float* __restrict__ x,
     const float* __restrict__ ln_g, const float* __restrict__ ln_b,
     const float* __restrict__ Wwqkv, const float* __restrict__ bwqkv)
{
    __shared__ float sfw[4096];
    __shared__ float sWL[8*65];
    __shared__ float sxb[8*64];
    int tid = threadIdx.x, warp = tid>>5, lane = tid&31;
    for (int idx = tid; idx < 4096; idx += 256) {
        int c = idx&3, l = (idx>>2)&31, d2 = idx>>7;
        int e = l + 32*(c&1);
        int d = 2*d2 + (c>>1);
        sfw[idx] = Wwqkv[8192 + e*64 + d];
    }
    for (int i = tid; i < 512; i += 256)
        sWL[(i>>6)*65 + (i&63)] = g_WL[i];
    __syncthreads();
    float ga0 = ln_g[lane], ga1 = ln_g[lane+32];
    float gb0 = ln_b[lane], gb1 = ln_b[lane+32];
    float bv0 = bwqkv[128+lane], bv1 = bwqkv[128+lane+32];
    int tok_base = blockIdx.x*64 + warp*8;
    int b = tok_base/NTOK;
    int hh = lane>>2, qq = lane&3;
    for (int t = 0; t < 8; t++) {
        int token = tok_base + t;
        float x0 = x[token*64 + lane];
        float x1 = x[token*64 + lane + 32];
        float s = x0 + x1, ss = x0*x0 + x1*x1;
        #pragma unroll
        for (int off = 16; off; off >>= 1) {
            s  += __shfl_xor_sync(0xffffffffu, s,  off);
            ss += __shfl_xor_sync(0xffffffffu, ss, off);
        }
        float mu = s*(1.f/64.f);
        float var = ss*(1.f/64.f) - mu*mu;
        float rstd = rsqrtf(var + 1e-5f);
        float xn0 = (x0-mu)*rstd*ga0 + gb0;
        float xn1 = (x1-mu)*rstd*ga1 + gb1;
        g_xn[(size_t)token*64+lane] = xn0;
        g_xn[(size_t)token*64+lane+32] = xn1;
        sxb[warp*64+lane] = xn0; sxb[warp*64+lane+32] = xn1;
        __syncwarp();
        ull acc = pack2(bv0, bv1);
        #pragma unroll 8
        for (int d2 = 0; d2 < 32; d2++) {
            float4 w = *(const float4*)(sfw + d2*128 + lane*4);
            float2 xp = *(const float2*)(sxb + warp*64 + 2*d2);
            ffma2(acc, pack2(xp.x, xp.x), pack2(w.x, w.y));
            ffma2(acc, pack2(xp.y, xp.y), pack2(w.z, w.w));
        }
        float v0, v1; unpack2(acc, v0, v1);
        int nn = token - b*NTOK;
        {
            int h0 = lane>>3, j0 = lane&7;
            g_v[((size_t)(b*8+h0)*NTOK + nn)*8 + j0] = v0;
            int h1 = (lane+32)>>3;
            g_v[((size_t)(b*8+h1)*NTOK + nn)*8 + j0] = v1;
        }
        {
            float a = 0.f;
            #pragma unroll
            for (int dd = 0; dd < 16; dd++)
                a += sxb[warp*64 + qq*16 + dd]*sWL[hh*65 + qq*16 + dd];
            a += __shfl_xor_sync(0xffffffffu, a, 1);
            a += __shfl_xor_sync(0xffffffffu, a, 2);
            if (qq == 0) g_logits[(b*8+hh)*NTOK + nn] = a + g_bL[hh];
        }
        __syncwarp();
    }
}

// ---------------- K2: quad sums — parallel sub-row scans, fp16 cls out ----------------
#define CSTR 2369
__global__ void __launch_bounds__(512) k_quad()
{
    extern __shared__ float s[];  // 9 * CSTR floats
    __shared__ float red[512];
    __shared__ float smv;
    int bid = blockIdx.x, tid = threadIdx.x;
    int b = bid>>3, h = bid&7;
    for (int p = tid; p < 2304; p += 512) {
        int y = p/48, xx = p - y*48;
        s[y*49+xx] = g_logits[bid*NTOK + p];
    }
    __syncthreads();
    float mloc = -1e30f;
    for (int p = tid; p < 2304; p += 512) {
        int y = p/48, xx = p - y*48;
        mloc = fmaxf(mloc, s[y*49+xx]);
    }
    red[tid] = mloc;
    __syncthreads();
    for (int st = 256; st; st >>= 1) {
        if (tid < st) red[tid] = fmaxf(red[tid], red[tid+st]);
        __syncthreads();
    }
    if (tid == 0) smv = fmaxf(red[0], g_clslogit[h]);
    __syncthreads();
    float m = smv;
    float ecls = __expf(g_clslogit[h] - m);
    for (int p = tid; p < 2304; p += 512) {
        int y = p/48, xx = p - y*48;
        int idx = y*49+xx;
        s[idx] = __expf(s[idx] - m);
    }
    __syncthreads();
    const float* vbase = g_v + (size_t)bid*NTOK*8;
    for (int p = tid; p < 2304; p += 512) {
        int y = p/48, xx = p - y*48;
        int base = y*49 + xx;
        float ev = s[base];
        float4 va = *(const float4*)(vbase + (size_t)p*8);
        float4 vb = *(const float4*)(vbase + (size_t)p*8 + 4);
        s[1*CSTR + base] = ev*va.x;
        s[2*CSTR + base] = ev*va.y;
        s[3*CSTR + base] = ev*va.z;
        s[4*CSTR + base] = ev*va.w;
        s[5*CSTR + base] = ev*vb.x;
        s[6*CSTR + base] = ev*vb.y;
        s[7*CSTR + base] = ev*vb.z;
        s[8*CSTR + base] = ev*vb.w;
    }
    __syncthreads();
    {
        int sub = tid & 7;
        for (int rid = tid>>3; rid < 432; rid += 64) {
            int ch = rid/48, y = rid - (rid/48)*48;
            float* row = s + ch*CSTR + y*49 + sub*6;
            float p0 = row[0], p1 = row[1], p2 = row[2];
            float p3 = row[3], p4 = row[4], p5 = row[5];
            p1 += p0; p2 += p1; p3 += p2; p4 += p3; p5 += p4;
            float inc = p5;
            #pragma unroll
            for (int d = 1; d < 8; d <<= 1) {
                float vsh = __shfl_up_sync(0xffffffffu, inc, d, 8);
                if (sub >= d) inc += vsh;
            }
            float off = inc - p5;
            row[0] = p0+off; row[1] = p1+off; row[2] = p2+off;
            row[3] = p3+off; row[4] = p4+off; row[5] = p5+off;
        }
    }
    __syncthreads();
    {
        int sub = tid & 7;
        for (int cid = tid>>3; cid < 432; cid += 64) {
            int ch = cid/48, xx = cid - (cid/48)*48;
            float* col = s + ch*CSTR + xx + sub*6*49;
            float p0 = col[0],     p1 = col[49],    p2 = col[98];
            float p3 = col[147],   p4 = col[196],   p5 = col[245];
            p1 += p0; p2 += p1; p3 += p2; p4 += p3; p5 += p4;
            float inc = p5;
            #pragma unroll
            for (int d = 1; d < 8; d <<= 1) {
                float vsh = __shfl_up_sync(0xffffffffu, inc, d, 8);
                if (sub >= d) inc += vsh;
            }
            float off = inc - p5;
            col[0]   = p0+off; col[49]  = p1+off; col[98]  = p2+off;
            col[147] = p3+off; col[196] = p4+off; col[245] = p5+off;
        }
    }
    __syncthreads();
    float vc[8];
    #pragma unroll
    for (int j = 0; j < 8; j++) vc[j] = g_vc[h*8+j];
    for (int p = tid; p < 2304; p += 512) {
        int y = p/48, xx = p - y*48;
        int iC  = y*49 + xx;
        int iRT = y*49 + 47;
        int iCB = 47*49 + xx;
        int iT  = 47*49 + 47;
        int iCm = iC - 1;
        int iUp = iC - 49;
        int iUR = iRT - 49;
        int iCL = iCB - 1;
        int iUL = iUp - 1;
        bool hx = xx > 0, hy = y > 0;
        float rd[4];
        {
            const float* C = s;
            float tl = C[iC];
            float tr = C[iRT] - (hx ? C[iCm] : 0.f);
            float bl = C[iCB] - (hy ? C[iUp] : 0.f);
            float br = C[iT] - (hy ? C[iUR] : 0.f) - (hx ? C[iCL] : 0.f) + ((hx&&hy) ? C[iUL] : 0.f);
            rd[0] = 1.f/(ecls+tl); rd[1] = 1.f/(ecls+tr);
            rd[2] = 1.f/(ecls+bl); rd[3] = 1.f/(ecls+br);
        }
        float out[4][8];
        #pragma unroll
        for (int j = 0; j < 8; j++) {
            const float* C = s + (1+j)*CSTR;
            float tl = C[iC];
            float tr = C[iRT] - (hx ? C[iCm] : 0.f);
            float bl = C[iCB] - (hy ? C[iUp] : 0.f);
            float br = C[iT] - (hy ? C[iUR] : 0.f) - (hx ? C[iCL] : 0.f) + ((hx&&hy) ? C[iUL] : 0.f);
            float base = ecls*vc[j];
            out[0][j] = (base+tl)*rd[0];
            out[1][j] = (base+tr)*rd[1];
            out[2][j] = (base+bl)*rd[2];
            out[3][j] = (base+br)*rd[3];
        }
        unsigned* op = g_clsh + ((size_t)(b*NTOK + p)*4)*32 + h*4;
        #pragma unroll
        for (int r = 0; r < 4; r++) {
            uint4 u;
            u.x = h2pack(out[r][0], out[r][1]);
            u.y = h2pack(out[r][2], out[r][3]);
            u.z = h2pack(out[r][4], out[r][5]);
            u.w = h2pack(out[r][6], out[r][7]);
            *(uint4*)(op + r*32) = u;
        }
    }
}

// ---------------- K3: fused epilogue — fp16 weights + fp16 cls, fp32 cmix, no shuffles ----
#define XS 68
__global__ void __launch_bounds__(256) k_epi(float* __restrict__ outp)
{
    extern __shared__ float s[];
    float*  sxn   = s;               // [64 f][XS]
    float*  scmix = s + 64*XS;       // [64 e][XS] fp32
    uint2*  wsP   = (uint2*)(s + 2*64*XS);
    uint2*  wsQ   = wsP + 1024;
    __shared__ float scv[64];
    int tid = threadIdx.x, warp = tid>>5, lane = tid&31;
    int tok0 = blockIdx.x*64;
    int tb = warp*8;

    if (tid < 64) {
        float a = g_cvec[tid];
        #pragma unroll
        for (int h = 0; h < 8; h++) a += g_cvecp[h*64+tid];
        scv[tid] = a;
    }
    for (int i = tid; i < 4096; i += 256) {
        int t = i>>6, d = i&63;
        sxn[d*XS + t] = g_xn[(size_t)(tok0+t)*64 + d];
    }

    ull accO[2][4];
    #pragma unroll
    for (int e = 0; e < 2; e++)
        #pragma unroll
        for (int pr = 0; pr < 4; pr++) accO[e][pr] = pack2(0.f, 0.f);

    for (int h = 0; h < 8; h++) {
        __syncthreads();
        for (int i = tid; i < 1024; i += 256) {
            wsP[i] = g_P4h[h*1024 + i];
            wsQ[i] = g_Q4h[h*1024 + i];
        }
        __syncthreads();

        // GEMV1 (scaled domain): aQ[0]→qp2[2l], aQ[1]→qp2[2l+1]
        ull aQ[2][4];
        #pragma unroll
        for (int pr = 0; pr < 4; pr++) { aQ[0][pr] = pack2(0.f,0.f); aQ[1][pr] = pack2(0.f,0.f); }
        #pragma unroll 8
        for (int f2 = 0; f2 < 32; f2++) {
            uint2 wp = wsP[f2*32 + lane];
            float2 wa = h2f2(wp.x);
            float2 wb = h2f2(wp.y);
            ull pa0 = pack2(wa.x, wa.x);
            ull pa1 = pack2(wa.y, wa.y);
            ull pb0 = pack2(wb.x, wb.x);
            ull pb1 = pack2(wb.y, wb.y);
            const ulonglong2* xr0 = (const ulonglong2*)(sxn + (2*f2)*XS + tb);
            const ulonglong2* xr1 = (const ulonglong2*)(sxn + (2*f2+1)*XS + tb);
            ulonglong2 xa = xr0[0], xb = xr0[1];
            ulonglong2 xc = xr1[0], xd = xr1[1];
            ffma2(aQ[0][0], xa.x, pa0); ffma2(aQ[0][1], xa.y, pa0);
            ffma2(aQ[0][2], xb.x, pa0); ffma2(aQ[0][3], xb.y, pa0);
            ffma2(aQ[1][0], xa.x, pa1); ffma2(aQ[1][1], xa.y, pa1);
            ffma2(aQ[1][2], xb.x, pa1); ffma2(aQ[1][3], xb.y, pa1);
            ffma2(aQ[0][0], xc.x, pb0); ffma2(aQ[0][1], xc.y, pb0);
            ffma2(aQ[0][2], xd.x, pb0); ffma2(aQ[0][3], xd.y, pb0);
            ffma2(aQ[1][0], xc.x, pb1); ffma2(aQ[1][1], xc.y, pb1);
            ffma2(aQ[1][2], xd.x, pb1); ffma2(aQ[1][3], xd.y, pb1);
        }
        float2 u2p = *(const float2*)(g_u2 + h*64 + 2*lane);
        float q0[8], q1[8];
        #pragma unroll
        for (int pr = 0; pr < 4; pr++) {
            float a0, a1, b0, b1;
            unpack2(aQ[0][pr], a0, a1);
            unpack2(aQ[1][pr], b0, b1);
            q0[2*pr]   = a0*WINV + u2p.x; q0[2*pr+1] = a1*WINV + u2p.x;
            q1[2*pr]   = b0*WINV + u2p.y; q1[2*pr+1] = b1*WINV + u2p.y;
        }

        // scores + softmax + cmix (fp16 cls pairs (2l,2l+1), no shuffles for q)
        float mb0[2], mb1[2];
        #pragma unroll
        for (int t = 0; t < 8; t++) {
            const unsigned* cp = g_clsh + ((size_t)(tok0 + tb + t)*4)*32 + lane;
            float2 c0 = h2f2(cp[0]);
            float2 c1 = h2f2(cp[32]);
            float2 c2 = h2f2(cp[64]);
            float2 c3 = h2f2(cp[96]);
            float sc0 = q0[t]*c0.x + q1[t]*c0.y;
            float sc1 = q0[t]*c1.x + q1[t]*c1.y;
            float sc2 = q0[t]*c2.x + q1[t]*c2.y;
            float sc3 = q0[t]*c3.x + q1[t]*c3.y;
            #pragma unroll
            for (int off = 16; off; off >>= 1) {
                sc0 += __shfl_xor_sync(0xffffffffu, sc0, off);
                sc1 += __shfl_xor_sync(0xffffffffu, sc1, off);
                sc2 += __shfl_xor_sync(0xffffffffu, sc2, off);
                sc3 += __shfl_xor_sync(0xffffffffu, sc3, off);
            }
            float mx = fmaxf(fmaxf(sc0,sc1), fmaxf(sc2,sc3));
            float e0 = __expf(sc0-mx), e1 = __expf(sc1-mx);
            float e2 = __expf(sc2-mx), e3 = __expf(sc3-mx);
            float inv = 1.f/(e0+e1+e2+e3);
            float a0 = e0*inv, a1 = e1*inv, a2 = e2*inv, a3 = e3*inv;
            mb0[t&1] = a0*c0.x + a1*c1.x + a2*c2.x + a3*c3.x;   // cmix[2l]
            mb1[t&1] = a0*c0.y + a1*c1.y + a2*c2.y + a3*c3.y;   // cmix[2l+1]
            if (t & 1) {
                *(float2*)(scmix + (2*lane)*XS   + tb + t - 1) = make_float2(mb0[0], mb0[1]);
                *(float2*)(scmix + (2*lane+1)*XS + tb + t - 1) = make_float2(mb1[0], mb1[1]);
            }
        }
        __syncwarp();

        // GEMV2 (scaled domain) — identical to R13 (fp32 scmix broadcasts)
        #pragma unroll 8
        for (int e2 = 0; e2 < 32; e2++) {
            uint2 wq = wsQ[e2*32 + lane];
            float2 wa = h2f2(wq.x);
            float2 wb = h2f2(wq.y);
            ull pa0 = pack2(wa.x, wa.x);
            ull pa1 = pack2(wa.y, wa.y);
            ull pb0 = pack2(wb.x, wb.x);
            ull pb1 = pack2(wb.y, wb.y);
            const ulonglong2* mr0 = (const ulonglong2*)(scmix + (2*e2)*XS + tb);
            const ulonglong2* mr1 = (const ulonglong2*)(scmix + (2*e2+1)*XS + tb);
            ulonglong2 ma = mr0[0], mb = mr0[1];
            ulonglong2 mc = mr1[0], md = mr1[1];
            ffma2(accO[0][0], ma.x, pa0); ffma2(accO[0][1], ma.y, pa0);
            ffma2(accO[0][2], mb.x, pa0); ffma2(accO[0][3], mb.y, pa0);
            ffma2(accO[1][0], ma.x, pa1); ffma2(accO[1][1], ma.y, pa1);
            ffma2(accO[1][2], mb.x, pa1); ffma2(accO[1][3], mb.y, pa1);
            ffma2(accO[0][0], mc.x, pb0); ffma2(accO[0][1], mc.y, pb0);
            ffma2(accO[0][2], md.x, pb0); ffma2(accO[0][3], md.y, pb0);
            ffma2(accO[1][0], mc.x, pb1); ffma2(accO[1][1], mc.y, pb1);
            ffma2(accO[1][2], md.x, pb1); ffma2(accO[1][3], md.y, pb1);
        }
    }

    float o0[8], o1[8];
    #pragma unroll
    for (int pr = 0; pr < 4; pr++) {
        unpack2(accO[0][pr], o0[2*pr], o0[2*pr+1]);
        unpack2(accO[1][pr], o1[2*pr], o1[2*pr+1]);
    }
    float c0 = scv[lane], c1 = scv[lane+32];
    #pragma unroll
    for (int t = 0; t < 8; t++) {
        outp[(size_t)(tok0+tb+t)*64 + lane]      = o0[t]*WINV + c0;
        outp[(size_t)(tok0+tb+t)*64 + lane + 32] = o1[t]*WINV + c1;
    }
}

// ---------------- launch ----------------
extern "C" void kernel_launch(void* const* d_in, const int* in_sizes, int n_in,
                              void* d_out, int out_size)
{
    const float* x      = (const float*)d_in[0];
    const float* ln_g   = (const float*)d_in[1];
    const float* ln_b   = (const float*)d_in[2];
    const float* Wqkv   = (const float*)d_in[3];
    const float* bqkv   = (const float*)d_in[4];
    const float* cls_t  = (const float*)d_in[5];
    const float* Wwqkv  = (const float*)d_in[6];
    const float* bwqkv  = (const float*)d_in[7];
    const float* Wwproj = (const float*)d_in[8];
    const float* bwproj = (const float*)d_in[9];
    const float* Wraq   = (const float*)d_in[10];
    const float* Wrak   = (const float*)d_in[11];
    const float* Wrav   = (const float*)d_in[12];
    const float* Wrao   = (const float*)d_in[13];
    const float* brao   = (const float*)d_in[14];
    const float* Wout   = (const float*)d_in[15];
    const float* bout   = (const float*)d_in[16];
    float* outp = (float*)d_out;

    int pre_smem  = 3*SBUF*4;                  // 49920 B
    int quad_smem = 9*CSTR*4;                  // 85284 B
    int epi_smem  = (2*64*XS)*4 + 2*1024*8;    // 34816 + 16384 = 51200 B
    cudaFuncSetAttribute(precomp, cudaFuncAttributeMaxDynamicSharedMemorySize, pre_smem);
    cudaFuncSetAttribute(k_quad,  cudaFuncAttributeMaxDynamicSharedMemorySize, quad_smem);
    cudaFuncSetAttribute(k_epi,   cudaFuncAttributeMaxDynamicSharedMemorySize, epi_smem);

    precomp<<<17, 256, pre_smem>>>(cls_t, Wwqkv, bwqkv, brao, Wout, bout,
                                   Wraq, Wrak, Wrao, Wrav, Wqkv, bqkv, Wwproj, bwproj);
    k_ln<<<TOKENS/64, 256>>>(x, ln_g, ln_b, Wwqkv, bwqkv);
    k_quad<<<BB*NHEADS, 512, quad_smem>>>();
    k_epi<<<TOKENS/64, 256, epi_smem>>>(outp);
}

// round 17
// speedup vs baseline: 1.1432x; 1.0216x over previous
#include <cuda_runtime.h>
#include <cuda_fp16.h>
#include <math.h>

#define BB 64
#define NTOK 2304
#define DD 64
#define NHEADS 8
#define TOKENS (BB*NTOK)   // 147456

#define WSCALE 4096.0f
#define WINV   (1.0f/4096.0f)

// ---------------- scratch (device globals; no allocations) ----------------
__device__ float g_xn[TOKENS*DD];                // [token][d]
__device__ __half g_vh[TOKENS*DD];               // fp16, head-major: [(b*8+h)*2304 + p]*8 + j
__device__ float g_logits[BB*NHEADS*NTOK];
__device__ unsigned g_clsh[(size_t)TOKENS*4*32]; // fp16x2: [tok][r][32 pairs (2k,2k+1)]
__device__ float g_WL[NHEADS*DD];
__device__ float g_bL[NHEADS];
__device__ float g_vc[DD];
__device__ float g_clslogit[NHEADS];
__device__ float g_cvec[DD];
__device__ float g_cvecp[NHEADS*DD];             // per-head bwproj fold
__device__ uint2 g_P4h[NHEADS*1024];   // fp16x4 scaled: [h][f2][lane] = cols (2l,2l+1)
__device__ uint2 g_Q4h[NHEADS*1024];   // fp16x4 scaled: [h][e2][lane] = cols (l,l+32)
__device__ float g_u2[NHEADS*DD];

__device__ __forceinline__ float kscale() { return 0.35355339059327373f; } // 8^-0.5

// ---------------- f32x2 / fp16 helpers ----------------
typedef unsigned long long ull;
__device__ __forceinline__ ull pack2(float x, float y) {
    ull r; asm("mov.b64 %0, {%1,%2};" : "=l"(r) : "f"(x), "f"(y)); return r;
}
__device__ __forceinline__ void unpack2(ull v, float& x, float& y) {
    asm("mov.b64 {%0,%1}, %2;" : "=f"(x), "=f"(y) : "l"(v));
}
__device__ __forceinline__ void ffma2(ull& acc, ull a, ull b) {
    asm("fma.rn.f32x2 %0, %1, %2, %0;" : "+l"(acc) : "l"(a), "l"(b));
}
__device__ __forceinline__ unsigned h2pack(float a, float b) {
    __half2 h = __floats2half2_rn(a, b);
    return *reinterpret_cast<unsigned*>(&h);
}
__device__ __forceinline__ float2 h2f2(unsigned h) {
    __half2 hh = *reinterpret_cast<__half2*>(&h);
    return __half22float2(hh);
}

#define SBUF 4160   // padded 64x64 buffer

// ---------------- single precompute kernel: 17 blocks ----------------
__global__ void __launch_bounds__(256) precomp(
    const float* __restrict__ cls_tok,
    const float* __restrict__ Wwqkv, const float* __restrict__ bwqkv,
    const float* __restrict__ brao,
    const float* __restrict__ Wout, const float* __restrict__ bout,
    const float* __restrict__ Wraq, const float* __restrict__ Wrak,
    const float* __restrict__ Wrao, const float* __restrict__ Wrav,
    const float* __restrict__ Wqkv, const float* __restrict__ bqkv,
    const float* __restrict__ Wwproj, const float* __restrict__ bwproj)
{
    extern __shared__ float s[];
    float* s0 = s;
    float* s1 = s + SBUF;
    float* s2 = s + 2*SBUF;
    int bid = blockIdx.x, tid = threadIdx.x;

    if (bid == 0) {
        __shared__ float scq[192];
        __shared__ float sqc[64];
        __shared__ float sred[256];
        if (tid < 192) {
            float a = bwqkv[tid];
            for (int d = 0; d < 64; d++) a += Wwqkv[tid*64+d]*cls_tok[d];
            scq[tid] = a;
        }
        __syncthreads();
        if (tid < 64) { sqc[tid] = scq[tid]*kscale(); g_vc[tid] = scq[128+tid]; }
        __syncthreads();
        if (tid < 8) {
            float cl = 0.f, bl = 0.f;
            for (int j = 0; j < 8; j++) {
                cl += sqc[tid*8+j]*scq[64+tid*8+j];
                bl += sqc[tid*8+j]*bwqkv[64+tid*8+j];
            }
            g_clslogit[tid] = cl; g_bL[tid] = bl;
        }
        for (int i = tid; i < 512; i += 256) {
            int h = i>>6, d = i&63;
            float a = 0.f;
            for (int j = 0; j < 8; j++) a += sqc[h*8+j]*Wwqkv[(64+h*8+j)*64+d];
            g_WL[i] = a;
        }
        {
            int o = tid>>2, q = tid&3;
            float a = (q==0) ? bout[o] : 0.f;
            for (int k = q*128; k < q*128+128; k++) a += Wout[o*512+k]*brao[k&63];
            sred[tid] = a;
        }
        __syncthreads();
        if (tid < 64)
            g_cvec[tid] = sred[4*tid] + sred[4*tid+1] + sred[4*tid+2] + sred[4*tid+3];
    }
    else if (bid <= 8) {
        // ---- P side ----
        int h = bid - 1;
        __shared__ float su[64];
        for (int i = tid; i < 4096; i += 256) { s0[i] = Wraq[i]; s1[i] = Wrak[i]; }
        __syncthreads();
        for (int i = tid; i < 4096; i += 256) {           // G[dd][g] -> s2
            int dd = i>>6, g = i&63;
            float a = 0.f;
            #pragma unroll 8
            for (int e = 0; e < 64; e++) a += s0[e*64+dd]*s1[e*64+g];
            s2[i] = a;
        }
        __syncthreads();
        for (int i = tid; i < 4096; i += 256) s0[i] = Wqkv[h*4096 + i];
        __syncthreads();
        for (int i = tid; i < 4096; i += 256) {           // P[f][g] -> s1
            int f = i>>6, g = i&63;
            float a = 0.f;
            #pragma unroll 8
            for (int dd = 0; dd < 64; dd++) a += s0[dd*64+f]*s2[dd*64+g];
            s1[i] = a*kscale();
        }
        if (tid < 64) {
            float a = 0.f;
            for (int dd = 0; dd < 64; dd++) a += bqkv[h*64+dd]*s2[dd*64+tid];
            su[tid] = a*kscale();
        }
        __syncthreads();
        for (int i = tid; i < 4096; i += 256) s0[i] = Wwproj[i];
        __syncthreads();
        for (int i = tid; i < 4096; i += 256) {           // P2[f][e] -> s2
            int f = i>>6, e = i&63;
            float a = 0.f;
            #pragma unroll 8
            for (int g = 0; g < 64; g++) a += s1[f*64+g]*s0[g*64+e];
            s2[i] = a;
        }
        if (tid < 64) {
            float a = 0.f;
            for (int g = 0; g < 64; g++) a += su[g]*s0[g*64+tid];
            g_u2[h*64+tid] = a;
        }
        __syncthreads();
        // pack fp16 scaled, e-pairs (2l, 2l+1)
        for (int i = tid; i < 1024; i += 256) {
            int k2 = i>>5, l = i&31;
            uint2 u;
            u.x = h2pack(s2[(2*k2)*64 + 2*l]*WSCALE,   s2[(2*k2)*64 + 2*l+1]*WSCALE);
            u.y = h2pack(s2[(2*k2+1)*64 + 2*l]*WSCALE, s2[(2*k2+1)*64 + 2*l+1]*WSCALE);
            g_P4h[h*1024+i] = u;
        }
    }
    else {
        // ---- Q side ----
        int h = bid - 9;
        for (int i = tid; i < 4096; i += 256) { s0[i] = Wrao[i]; s1[i] = Wrav[i]; }
        __syncthreads();
        for (int i = tid; i < 4096; i += 256) {           // R[a][g] -> s2
            int a_ = i>>6, g = i&63;
            float a = 0.f;
            #pragma unroll 8
            for (int c = 0; c < 64; c++) a += s0[a_*64+c]*s1[c*64+g];
            s2[i] = a;
        }
        __syncthreads();
        for (int i = tid; i < 4096; i += 256) {
            int o = i>>6, a_ = i&63;
            s0[i] = Wout[o*512 + h*64 + a_];
        }
        __syncthreads();
        for (int i = tid; i < 4096; i += 256) {           // Qt[o][g] -> s1
            int o = i>>6, g = i&63;
            float a = 0.f;
            #pragma unroll 8
            for (int a_ = 0; a_ < 64; a_++) a += s0[o*64+a_]*s2[a_*64+g];
            s1[i] = a;
        }
        __syncthreads();
        if (tid < 64) {
            float a = 0.f;
            for (int g = 0; g < 64; g++) a += bwproj[g]*s1[tid*64+g];
            g_cvecp[h*64+tid] = a;
        }
        for (int i = tid; i < 4096; i += 256) s0[i] = Wwproj[i];
        __syncthreads();
        for (int i = tid; i < 4096; i += 256) {           // Q2t[o][e] -> s2 (65-stride)
            int o = i>>6, e = i&63;
            float a = 0.f;
            #pragma unroll 8
            for (int g = 0; g < 64; g++) a += s0[g*64+e]*s1[o*64+g];
            s2[o*65+e] = a;
        }
        __syncthreads();
        // pack fp16 scaled: Q2[e][o], o-pairs (l, l+32)
        for (int i = tid; i < 1024; i += 256) {
            int k2 = i>>5, l = i&31;
            uint2 u;
            u.x = h2pack(s2[l*65 + 2*k2]*WSCALE,     s2[(l+32)*65 + 2*k2]*WSCALE);
            u.y = h2pack(s2[l*65 + 2*k2 + 1]*WSCALE, s2[(l+32)*65 + 2*k2 + 1]*WSCALE);
            g_Q4h[h*1024+i] = u;
        }
    }
}

// ---------------- K1: LayerNorm + logits + v projection (fp16 weights, fp16 v) ----------
__global__ void __launch_bounds__(256) k_ln(const float* __restrict__ x,
     const float* __restrict__ ln_g, const float* __restrict__ ln_b,
     const float* __restrict__ Wwqkv, const float* __restrict__ bwqkv)
{
    __shared__ unsigned sfw16[2048];  // uint2 [d2][lane]: halves (W[l][2d2],W[l+32][2d2] | ..2d2+1)
    __shared__ float sWL[8*65];
    __shared__ float sxb[8*64];
    int tid = threadIdx.x, warp = tid>>5, lane = tid&31;
    for (int i = tid; i < 1024; i += 256) {
        int d2 = i>>5, l = i&31;
        unsigned ux = h2pack(Wwqkv[8192 + l*64 + 2*d2],     Wwqkv[8192 + (l+32)*64 + 2*d2]);
        unsigned uy = h2pack(Wwqkv[8192 + l*64 + 2*d2 + 1], Wwqkv[8192 + (l+32)*64 + 2*d2 + 1]);
        *(uint2*)(sfw16 + 2*i) = make_uint2(ux, uy);
    }
    for (int i = tid; i < 512; i += 256)
        sWL[(i>>6)*65 + (i&63)] = g_WL[i];
    __syncthreads();
    float ga0 = ln_g[lane], ga1 = ln_g[lane+32];
    float gb0 = ln_b[lane], gb1 = ln_b[lane+32];
    float bv0 = bwqkv[128+lane], bv1 = bwqkv[128+lane+32];
    int tok_base = blockIdx.x*64 + warp*8;
    int b = tok_base/NTOK;
    int hh = lane>>2, qq = lane&3;
    for (int t = 0; t < 8; t++) {
        int token = tok_base + t;
        float x0 = x[token*64 + lane];
        float x1 = x[token*64 + lane + 32];
        float s = x0 + x1, ss = x0*x0 + x1*x1;
        #pragma unroll
        for (int off = 16; off; off >>= 1) {
            s  += __shfl_xor_sync(0xffffffffu, s,  off);
            ss += __shfl_xor_sync(0xffffffffu, ss, off);
        }
        float mu = s*(1.f/64.f);
        float var = ss*(1.f/64.f) - mu*mu;
        float rstd = rsqrtf(var + 1e-5f);
        float xn0 = (x0-mu)*rstd*ga0 + gb0;
        float xn1 = (x1-mu)*rstd*ga1 + gb1;
        g_xn[(size_t)token*64+lane] = xn0;
        g_xn[(size_t)token*64+lane+32] = xn1;
        sxb[warp*64+lane] = xn0; sxb[warp*64+lane+32] = xn1;
        __syncwarp();
        ull acc = pack2(bv0, bv1);
        #pragma unroll 8
        for (int d2 = 0; d2 < 32; d2++) {
            uint2 wp = *(const uint2*)(sfw16 + d2*64 + lane*2);
            float2 xp = *(const float2*)(sxb + warp*64 + 2*d2);
            float2 wa = h2f2(wp.x);
            float2 wb = h2f2(wp.y);
            ffma2(acc, pack2(xp.x, xp.x), pack2(wa.x, wa.y));
            ffma2(acc, pack2(xp.y, xp.y), pack2(wb.x, wb.y));
        }
        float v0, v1; unpack2(acc, v0, v1);
        int nn = token - b*NTOK;
        {
            int h0 = lane>>3, j0 = lane&7;
            g_vh[((size_t)(b*8+h0)*NTOK + nn)*8 + j0] = __float2half(v0);
            int h1 = (lane+32)>>3;
            g_vh[((size_t)(b*8+h1)*NTOK + nn)*8 + j0] = __float2half(v1);
        }
        {
            float a = 0.f;
            #pragma unroll
            for (int dd = 0; dd < 16; dd++)
                a += sxb[warp*64 + qq*16 + dd]*sWL[hh*65 + qq*16 + dd];
            a += __shfl_xor_sync(0xffffffffu, a, 1);
            a += __shfl_xor_sync(0xffffffffu, a, 2);
            if (qq == 0) g_logits[(b*8+hh)*NTOK + nn] = a + g_bL[hh];
        }
        __syncwarp();
    }
}

// ---------------- K2: quad sums — parallel sub-row scans, fp16 v in, fp16 cls out ------
#define CSTR 2369
__global__ void __launch_bounds__(512) k_quad()
{
    extern __shared__ float s[];  // 9 * CSTR floats
    __shared__ float red[512];
    __shared__ float smv;
    int bid = blockIdx.x, tid = threadIdx.x;
    int b = bid>>3, h = bid&7;
    for (int p = tid; p < 2304; p += 512) {
        int y = p/48, xx = p - y*48;
        s[y*49+xx] = g_logits[bid*NTOK + p];
    }
    __syncthreads();
    float mloc = -1e30f;
    for (int p = tid; p < 2304; p += 512) {
        int y = p/48, xx = p - y*48;
        mloc = fmaxf(mloc, s[y*49+xx]);
    }
    red[tid] = mloc;
    __syncthreads();
    for (int st = 256; st; st >>= 1) {
        if (tid < st) red[tid] = fmaxf(red[tid], red[tid+st]);
        __syncthreads();
    }
    if (tid == 0) smv = fmaxf(red[0], g_clslogit[h]);
    __syncthreads();
    float m = smv;
    float ecls = __expf(g_clslogit[h] - m);
    for (int p = tid; p < 2304; p += 512) {
        int y = p/48, xx = p - y*48;
        int idx = y*49+xx;
        s[idx] = __expf(s[idx] - m);
    }
    __syncthreads();
    const __half* vbase = g_vh + (size_t)bid*NTOK*8;
    for (int p = tid; p < 2304; p += 512) {
        int y = p/48, xx = p - y*48;
        int base = y*49 + xx;
        float ev = s[base];
        uint4 vv = *(const uint4*)(vbase + (size_t)p*8);
        float2 va = h2f2(vv.x), vb = h2f2(vv.y);
        float2 vc2 = h2f2(vv.z), vd = h2f2(vv.w);
        s[1*CSTR + base] = ev*va.x;
        s[2*CSTR + base] = ev*va.y;
        s[3*CSTR + base] = ev*vb.x;
        s[4*CSTR + base] = ev*vb.y;
        s[5*CSTR + base] = ev*vc2.x;
        s[6*CSTR + base] = ev*vc2.y;
        s[7*CSTR + base] = ev*vd.x;
        s[8*CSTR + base] = ev*vd.y;
    }
    __syncthreads();
    {
        int sub = tid & 7;
        for (int rid = tid>>3; rid < 432; rid += 64) {
            int ch = rid/48, y = rid - (rid/48)*48;
            float* row = s + ch*CSTR + y*49 + sub*6;
            float p0 = row[0], p1 = row[1], p2 = row[2];
            float p3 = row[3], p4 = row[4], p5 = row[5];
            p1 += p0; p2 += p1; p3 += p2; p4 += p3; p5 += p4;
            float inc = p5;
            #pragma unroll
            for (int d = 1; d < 8; d <<= 1) {
                float vsh = __shfl_up_sync(0xffffffffu, inc, d, 8);
                if (sub >= d) inc += vsh;
            }
            float off = inc - p5;
            row[0] = p0+off; row[1] = p1+off; row[2] = p2+off;
            row[3] = p3+off; row[4] = p4+off; row[5] = p5+off;
        }
    }
    __syncthreads();
    {
        int sub = tid & 7;
        for (int cid = tid>>3; cid < 432; cid += 64) {
            int ch = cid/48, xx = cid - (cid/48)*48;
            float* col = s + ch*CSTR + xx + sub*6*49;
            float p0 = col[0],     p1 = col[49],    p2 = col[98];
            float p3 = col[147],   p4 = col[196],   p5 = col[245];
            p1 += p0; p2 += p1; p3 += p2; p4 += p3; p5 += p4;
            float inc = p5;
            #pragma unroll
            for (int d = 1; d < 8; d <<= 1) {
                float vsh = __shfl_up_sync(0xffffffffu, inc, d, 8);
                if (sub >= d) inc += vsh;
            }
            float off = inc - p5;
            col[0]   = p0+off; col[49]  = p1+off; col[98]  = p2+off;
            col[147] = p3+off; col[196] = p4+off; col[245] = p5+off;
        }
    }
    __syncthreads();
    float vc[8];
    #pragma unroll
    for (int j = 0; j < 8; j++) vc[j] = g_vc[h*8+j];
    for (int p = tid; p < 2304; p += 512) {
        int y = p/48, xx = p - y*48;
        int iC  = y*49 + xx;
        int iRT = y*49 + 47;
        int iCB = 47*49 + xx;
        int iT  = 47*49 + 47;
        int iCm = iC - 1;
        int iUp = iC - 49;
        int iUR = iRT - 49;
        int iCL = iCB - 1;
        int iUL = iUp - 1;
        bool hx = xx > 0, hy = y > 0;
        float rd[4];
        {
            const float* C = s;
            float tl = C[iC];
            float tr = C[iRT] - (hx ? C[iCm] : 0.f);
            float bl = C[iCB] - (hy ? C[iUp] : 0.f);
            float br = C[iT] - (hy ? C[iUR] : 0.f) - (hx ? C[iCL] : 0.f) + ((hx&&hy) ? C[iUL] : 0.f);
            rd[0] = 1.f/(ecls+tl); rd[1] = 1.f/(ecls+tr);
            rd[2] = 1.f/(ecls+bl); rd[3] = 1.f/(ecls+br);
        }
        float out[4][8];
        #pragma unroll
        for (int j = 0; j < 8; j++) {
            const float* C = s + (1+j)*CSTR;
            float tl = C[iC];
            float tr = C[iRT] - (hx ? C[iCm] : 0.f);
            float bl = C[iCB] - (hy ? C[iUp] : 0.f);
            float br = C[iT] - (hy ? C[iUR] : 0.f) - (hx ? C[iCL] : 0.f) + ((hx&&hy) ? C[iUL] : 0.f);
            float base = ecls*vc[j];
            out[0][j] = (base+tl)*rd[0];
            out[1][j] = (base+tr)*rd[1];
            out[2][j] = (base+bl)*rd[2];
            out[3][j] = (base+br)*rd[3];
        }
        unsigned* op = g_clsh + ((size_t)(b*NTOK + p)*4)*32 + h*4;
        #pragma unroll
        for (int r = 0; r < 4; r++) {
            uint4 u;
            u.x = h2pack(out[r][0], out[r][1]);
            u.y = h2pack(out[r][2], out[r][3]);
            u.z = h2pack(out[r][4], out[r][5]);
            u.w = h2pack(out[r][6], out[r][7]);
            *(uint4*)(op + r*32) = u;
        }
    }
}

// ---------------- K3: fused epilogue — fp16 weights + fp16 cls, fp32 cmix (R16) ----
#define XS 68
__global__ void __launch_bounds__(256) k_epi(float* __restrict__ outp)
{
    extern __shared__ float s[];
    float*  sxn   = s;               // [64 f][XS]
    float*  scmix = s + 64*XS;       // [64 e][XS] fp32
    uint2*  wsP   = (uint2*)(s + 2*64*XS);
    uint2*  wsQ   = wsP + 1024;
    __shared__ float scv[64];
    int tid = threadIdx.x, warp = tid>>5, lane = tid&31;
    int tok0 = blockIdx.x*64;
    int tb = warp*8;

    if (tid < 64) {
        float a = g_cvec[tid];
        #pragma unroll
        for (int h = 0; h < 8; h++) a += g_cvecp[h*64+tid];
        scv[tid] = a;
    }
    for (int i = tid; i < 4096; i += 256) {
        int t = i>>6, d = i&63;
        sxn[d*XS + t] = g_xn[(size_t)(tok0+t)*64 + d];
    }

    ull accO[2][4];
    #pragma unroll
    for (int e = 0; e < 2; e++)
        #pragma unroll
        for (int pr = 0; pr < 4; pr++) accO[e][pr] = pack2(0.f, 0.f);

    for (int h = 0; h < 8; h++) {
        __syncthreads();
        for (int i = tid; i < 1024; i += 256) {
            wsP[i] = g_P4h[h*1024 + i];
            wsQ[i] = g_Q4h[h*1024 + i];
        }
        __syncthreads();

        // GEMV1 (scaled domain): aQ[0]→qp2[2l], aQ[1]→qp2[2l+1]
        ull aQ[2][4];
        #pragma unroll
        for (int pr = 0; pr < 4; pr++) { aQ[0][pr] = pack2(0.f,0.f); aQ[1][pr] = pack2(0.f,0.f); }
        #pragma unroll 8
        for (int f2 = 0; f2 < 32; f2++) {
            uint2 wp = wsP[f2*32 + lane];
            float2 wa = h2f2(wp.x);
            float2 wb = h2f2(wp.y);
            ull pa0 = pack2(wa.x, wa.x);
            ull pa1 = pack2(wa.y, wa.y);
            ull pb0 = pack2(wb.x, wb.x);
            ull pb1 = pack2(wb.y, wb.y);
            const ulonglong2* xr0 = (const ulonglong2*)(sxn + (2*f2)*XS + tb);
            const ulonglong2* xr1 = (const ulonglong2*)(sxn + (2*f2+1)*XS + tb);
            ulonglong2 xa = xr0[0], xb = xr0[1];
            ulonglong2 xc = xr1[0], xd = xr1[1];
            ffma2(aQ[0][0], xa.x, pa0); ffma2(aQ[0][1], xa.y, pa0);
            ffma2(aQ[0][2], xb.x, pa0); ffma2(aQ[0][3], xb.y, pa0);
            ffma2(aQ[1][0], xa.x, pa1); ffma2(aQ[1][1], xa.y, pa1);
            ffma2(aQ[1][2], xb.x, pa1); ffma2(aQ[1][3], xb.y, pa1);
            ffma2(aQ[0][0], xc.x, pb0); ffma2(aQ[0][1], xc.y, pb0);
            ffma2(aQ[0][2], xd.x, pb0); ffma2(aQ[0][3], xd.y, pb0);
            ffma2(aQ[1][0], xc.x, pb1); ffma2(aQ[1][1], xc.y, pb1);
            ffma2(aQ[1][2], xd.x, pb1); ffma2(aQ[1][3], xd.y, pb1);
        }
        float2 u2p = *(const float2*)(g_u2 + h*64 + 2*lane);
        float q0[8], q1[8];
        #pragma unroll
        for (int pr = 0; pr < 4; pr++) {
            float a0, a1, b0, b1;
            unpack2(aQ[0][pr], a0, a1);
            unpack2(aQ[1][pr], b0, b1);
            q0[2*pr]   = a0*WINV + u2p.x; q0[2*pr+1] = a1*WINV + u2p.x;
            q1[2*pr]   = b0*WINV + u2p.y; q1[2*pr+1] = b1*WINV + u2p.y;
        }

        // scores + softmax + cmix (fp16 cls pairs (2l,2l+1), no shuffles for q)
        float mb0[2], mb1[2];
        #pragma unroll
        for (int t = 0; t < 8; t++) {
            const unsigned* cp = g_clsh + ((size_t)(tok0 + tb + t)*4)*32 + lane;
            float2 c0 = h2f2(cp[0]);
            float2 c1 = h2f2(cp[32]);
            float2 c2 = h2f2(cp[64]);
            float2 c3 = h2f2(cp[96]);
            float sc0 = q0[t]*c0.x + q1[t]*c0.y;
            float sc1 = q0[t]*c1.x + q1[t]*c1.y;
            float sc2 = q0[t]*c2.x + q1[t]*c2.y;
            float sc3 = q0[t]*c3.x + q1[t]*c3.y;
            #pragma unroll
            for (int off = 16; off; off >>= 1) {
                sc0 += __shfl_xor_sync(0xffffffffu, sc0, off);
                sc1 += __shfl_xor_sync(0xffffffffu, sc1, off);
                sc2 += __shfl_xor_sync(0xffffffffu, sc2, off);
                sc3 += __shfl_xor_sync(0xffffffffu, sc3, off);
            }
            float mx = fmaxf(fmaxf(sc0,sc1), fmaxf(sc2,sc3));
            float e0 = __expf(sc0-mx), e1 = __expf(sc1-mx);
            float e2 = __expf(sc2-mx), e3 = __expf(sc3-mx);
            float inv = 1.f/(e0+e1+e2+e3);
            float a0 = e0*inv, a1 = e1*inv, a2 = e2*inv, a3 = e3*inv;
            mb0[t&1] = a0*c0.x + a1*c1.x + a2*c2.x + a3*c3.x;   // cmix[2l]
            mb1[t&1] = a0*c0.y + a1*c1.y + a2*c2.y + a3*c3.y;   // cmix[2l+1]
            if (t & 1) {
                *(float2*)(scmix + (2*lane)*XS   + tb + t - 1) = make_float2(mb0[0], mb0[1]);
                *(float2*)(scmix + (2*lane+1)*XS + tb + t - 1) = make_float2(mb1[0], mb1[1]);
            }
        }
        __syncwarp();

        // GEMV2 (scaled domain) — fp32 scmix broadcasts
        #pragma unroll 8
        for (int e2 = 0; e2 < 32; e2++) {
            uint2 wq = wsQ[e2*32 + lane];
            float2 wa = h2f2(wq.x);
            float2 wb = h2f2(wq.y);
            ull pa0 = pack2(wa.x, wa.x);
            ull pa1 = pack2(wa.y, wa.y);
            ull pb0 = pack2(wb.x, wb.x);
            ull pb1 = pack2(wb.y, wb.y);
            const ulonglong2* mr0 = (const ulonglong2*)(scmix + (2*e2)*XS + tb);
            const ulonglong2* mr1 = (const ulonglong2*)(scmix + (2*e2+1)*XS + tb);
            ulonglong2 ma = mr0[0], mb = mr0[1];
            ulonglong2 mc = mr1[0], md = mr1[1];
            ffma2(accO[0][0], ma.x, pa0); ffma2(accO[0][1], ma.y, pa0);
            ffma2(accO[0][2], mb.x, pa0); ffma2(accO[0][3], mb.y, pa0);
            ffma2(accO[1][0], ma.x, pa1); ffma2(accO[1][1], ma.y, pa1);
            ffma2(accO[1][2], mb.x, pa1); ffma2(accO[1][3], mb.y, pa1);
            ffma2(accO[0][0], mc.x, pb0); ffma2(accO[0][1], mc.y, pb0);
            ffma2(accO[0][2], md.x, pb0); ffma2(accO[0][3], md.y, pb0);
            ffma2(accO[1][0], mc.x, pb1); ffma2(accO[1][1], mc.y, pb1);
            ffma2(accO[1][2], md.x, pb1); ffma2(accO[1][3], md.y, pb1);
        }
    }

    float o0[8], o1[8];
    #pragma unroll
    for (int pr = 0; pr < 4; pr++) {
        unpack2(accO[0][pr], o0[2*pr], o0[2*pr+1]);
        unpack2(accO[1][pr], o1[2*pr], o1[2*pr+1]);
    }
    float c0 = scv[lane], c1 = scv[lane+32];
    #pragma unroll
    for (int t = 0; t < 8; t++) {
        outp[(size_t)(tok0+tb+t)*64 + lane]      = o0[t]*WINV + c0;
        outp[(size_t)(tok0+tb+t)*64 + lane + 32] = o1[t]*WINV + c1;
    }
}

// ---------------- launch ----------------
extern "C" void kernel_launch(void* const* d_in, const int* in_sizes, int n_in,
                              void* d_out, int out_size)
{
    const float* x      = (const float*)d_in[0];
    const float* ln_g   = (const float*)d_in[1];
    const float* ln_b   = (const float*)d_in[2];
    const float* Wqkv   = (const float*)d_in[3];
    const float* bqkv   = (const float*)d_in[4];
    const float* cls_t  = (const float*)d_in[5];
    const float* Wwqkv  = (const float*)d_in[6];
    const float* bwqkv  = (const float*)d_in[7];
    const float* Wwproj = (const float*)d_in[8];
    const float* bwproj = (const float*)d_in[9];
    const float* Wraq   = (const float*)d_in[10];
    const float* Wrak   = (const float*)d_in[11];
    const float* Wrav   = (const float*)d_in[12];
    const float* Wrao   = (const float*)d_in[13];
    const float* brao   = (const float*)d_in[14];
    const float* Wout   = (const float*)d_in[15];
    const float* bout   = (const float*)d_in[16];
    float* outp = (float*)d_out;

    int pre_smem  = 3*SBUF*4;                  // 49920 B
    int quad_smem = 9*CSTR*4;                  // 85284 B
    int epi_smem  = (2*64*XS)*4 + 2*1024*8;    // 34816 + 16384 = 51200 B
    cudaFuncSetAttribute(precomp, cudaFuncAttributeMaxDynamicSharedMemorySize, pre_smem);
    cudaFuncSetAttribute(k_quad,  cudaFuncAttributeMaxDynamicSharedMemorySize, quad_smem);
    cudaFuncSetAttribute(k_epi,   cudaFuncAttributeMaxDynamicSharedMemorySize, epi_smem);

    precomp<<<17, 256, pre_smem>>>(cls_t, Wwqkv, bwqkv, brao, Wout, bout,
                                   Wraq, Wrak, Wrao, Wrav, Wqkv, bqkv, Wwproj, bwproj);
    k_ln<<<TOKENS/64, 256>>>(x, ln_g, ln_b, Wwqkv, bwqkv);
    k_quad<<<BB*NHEADS, 512, quad_smem>>>();
    k_epi<<<TOKENS/64, 256, epi_smem>>>(outp);
}